// round 3
// baseline (speedup 1.0000x reference)
#include <cuda_runtime.h>
#include <cstdint>

// Problem shape (fixed by the dataset)
#define BB   2
#define LLEN 4096
#define KK   32
#define BLN  (BB * LLEN)   // 8192 residues
#define HALF 128
#define F_EPS 1e-6f

// -------- scratch (device globals; no allocations allowed) --------
__device__ float g_R  [BLN * 9];      // per-residue rotation (R[m][n] = e_{n}[m]), masked
__device__ float g_t  [BLN * 3];      // per-residue translation (mask * CA)
__device__ float g_gA [BLN * HALF];   // const + intra-i partial fourier arg
__device__ float g_hB [BLN * HALF];   // intra-j partial fourier arg
__device__ float g_Wc [16 * HALF];    // combined cross-pair W rows
__device__ float g_WiA[ 6 * HALF];    // combined intra-i W rows
__device__ float g_WiB[ 6 * HALF];    // combined intra-j W rows
__device__ float g_cw [HALF];         // sqrt(EPS)*sum of diagonal W rows

// sin(2*pi*y), cos(2*pi*y) via range reduction + Taylor on [-pi/2, pi/2].
// abs error <= ~2.5e-5 (cos), ~3.6e-6 (sin) — well inside 1e-3 budget.
__device__ __forceinline__ void sincos2pi(float y, float& s, float& c) {
    int   k  = __float2int_rn(2.0f * y);
    float kf = (float)k;
    float g  = fmaf(kf, -0.5f, y);          // |g| <= 0.25
    float t  = g * g;
    float cp = fmaf(60.2446414f, t, -85.4568172f);
    cp = fmaf(cp, t, 64.9393940f);
    cp = fmaf(cp, t, -19.7392088f);
    cp = fmaf(cp, t, 1.0f);
    float sp = fmaf(42.0586939f, t, -76.7058598f);
    sp = fmaf(sp, t, 81.6052493f);
    sp = fmaf(sp, t, -41.3417022f);
    sp = fmaf(sp, t, 6.28318531f);
    sp *= g;
    unsigned sgn = ((unsigned)k) << 31;      // parity of k flips both signs
    c = __uint_as_float(__float_as_uint(cp) ^ sgn);
    s = __uint_as_float(__float_as_uint(sp) ^ sgn);
}

// -------- phase 0: combine W_dist rows (symmetric pairs) --------
__global__ void k_prep_w(const float* __restrict__ Wd) {
    int e = threadIdx.x;                      // 0..127
    float cw = 0.f;
#pragma unroll
    for (int a = 0; a < 8; a++) cw += Wd[(a * 8 + a) * HALF + e];
    g_cw[e] = cw * sqrtf(F_EPS);

    const int pa[6] = {0, 0, 0, 1, 1, 2};
    const int pb[6] = {1, 2, 3, 2, 3, 3};
#pragma unroll
    for (int u = 0; u < 6; u++) {
        int a = pa[u], b = pb[u];
        g_WiA[u * HALF + e] = Wd[(a * 8 + b) * HALF + e] + Wd[(b * 8 + a) * HALF + e];
        g_WiB[u * HALF + e] = Wd[((a + 4) * 8 + (b + 4)) * HALF + e]
                            + Wd[((b + 4) * 8 + (a + 4)) * HALF + e];
    }
#pragma unroll
    for (int p = 0; p < 4; p++)
#pragma unroll
        for (int q = 0; q < 4; q++)
            g_Wc[(p * 4 + q) * HALF + e] =
                Wd[(p * 8 + (q + 4)) * HALF + e] + Wd[((q + 4) * 8 + p) * HALF + e];
}

// -------- phase 1: per-residue frames + intra partial sums --------
__global__ void k_residue(const float* __restrict__ X, const int* __restrict__ Cm) {
    int bl = blockIdx.x;
    int e  = threadIdx.x;                     // 0..127 (output channel)
    __shared__ float sXi[12];
    if (e < 12) sXi[e] = X[bl * 12 + e];
    __syncthreads();

    float N0 = sXi[0], N1 = sXi[1],  N2 = sXi[2];
    float A0 = sXi[3], A1 = sXi[4],  A2 = sXi[5];
    float C0 = sXi[6], C1 = sXi[7],  C2 = sXi[8];

    // e1 = normalize(N - CA)
    float v0 = N0 - A0, v1 = N1 - A1, v2 = N2 - A2;
    float inv = 1.0f / (sqrtf(v0 * v0 + v1 * v1 + v2 * v2) + F_EPS);
    float e10 = v0 * inv, e11 = v1 * inv, e12 = v2 * inv;
    // u2 = normalize(C - CA)
    float u0 = C0 - A0, u1 = C1 - A1, u2 = C2 - A2;
    inv = 1.0f / (sqrtf(u0 * u0 + u1 * u1 + u2 * u2) + F_EPS);
    u0 *= inv; u1 *= inv; u2 *= inv;
    // e2 = normalize(u2 - (u2.e1) e1)
    float d  = u0 * e10 + u1 * e11 + u2 * e12;
    float w0 = u0 - d * e10, w1 = u1 - d * e11, w2 = u2 - d * e12;
    inv = 1.0f / (sqrtf(w0 * w0 + w1 * w1 + w2 * w2) + F_EPS);
    float e20 = w0 * inv, e21 = w1 * inv, e22 = w2 * inv;
    // e3 = cross(e1, e2)
    float e30 = e11 * e22 - e12 * e21;
    float e31 = e12 * e20 - e10 * e22;
    float e32 = e10 * e21 - e11 * e20;

    float mask = (Cm[bl] > 0) ? 1.0f : 0.0f;

    if (e == 0) {
        // R[m][n] = e_{n}[m], stored row-major m*3+n, masked
        g_R[bl * 9 + 0] = e10 * mask; g_R[bl * 9 + 1] = e20 * mask; g_R[bl * 9 + 2] = e30 * mask;
        g_R[bl * 9 + 3] = e11 * mask; g_R[bl * 9 + 4] = e21 * mask; g_R[bl * 9 + 5] = e31 * mask;
        g_R[bl * 9 + 6] = e12 * mask; g_R[bl * 9 + 7] = e22 * mask; g_R[bl * 9 + 8] = e32 * mask;
        g_t[bl * 3 + 0] = A0 * mask;  g_t[bl * 3 + 1] = A1 * mask;  g_t[bl * 3 + 2] = A2 * mask;
    }

    // 6 intra-atom distances of this residue
    const int pa[6] = {0, 0, 0, 1, 1, 2};
    const int pb[6] = {1, 2, 3, 2, 3, 3};
    float d6[6];
#pragma unroll
    for (int u = 0; u < 6; u++) {
        int a = pa[u] * 3, b = pb[u] * 3;
        float dx = sXi[a + 0] - sXi[b + 0];
        float dy = sXi[a + 1] - sXi[b + 1];
        float dz = sXi[a + 2] - sXi[b + 2];
        d6[u] = sqrtf(fmaf(dx, dx, fmaf(dy, dy, fmaf(dz, dz, F_EPS))));
    }
    float gA = g_cw[e];
    float hB = 0.f;
#pragma unroll
    for (int u = 0; u < 6; u++) {
        gA = fmaf(d6[u], g_WiA[u * HALF + e], gA);
        hB = fmaf(d6[u], g_WiB[u * HALF + e], hB);
    }
    g_gA[bl * HALF + e] = gA;
    g_hB[bl * HALF + e] = hB;
}

// -------- phase 2: per-edge fourier features --------
__global__ __launch_bounds__(128) void k_edges(
    const float* __restrict__ X,
    const int*   __restrict__ eidx,
    const float* __restrict__ Wvec,
    float*       __restrict__ out)
{
    int bl = blockIdx.x;
    int e  = threadIdx.x;                      // output channel 0..127
    int b  = bl >> 12;                         // L = 4096

    __shared__ float sXi[12], sR[9], st[3];
    __shared__ int   sj[KK];
    __shared__ float sD[2][16];
    __shared__ float sT[2][4];

    if (e < 12) sXi[e] = X[bl * 12 + e];
    if (e < 9)  sR[e]  = g_R[bl * 9 + e];
    if (e < 3)  st[e]  = g_t[bl * 3 + e];
    if (e < KK) sj[e]  = eidx[bl * KK + e];

    float Wc[16], Wv[3];
#pragma unroll
    for (int c = 0; c < 16; c++) Wc[c] = g_Wc[c * HALF + e];
    Wv[0] = Wvec[e];
    Wv[1] = Wvec[HALF + e];
    Wv[2] = Wvec[2 * HALF + e];
    float gA = g_gA[bl * HALF + e];
    __syncthreads();

    for (int k = 0; k < KK; k++) {
        int buf = k & 1;
        int j   = sj[k];
        int jb  = (b << 12) + j;

        float hBj = g_hB[jb * HALF + e];       // issue early (L2 latency overlap)

        if (e < 16) {
            int p = e >> 2, q = e & 3;
            const float* Xj = X + jb * 12 + q * 3;
            float dx = sXi[p * 3 + 0] - Xj[0];
            float dy = sXi[p * 3 + 1] - Xj[1];
            float dz = sXi[p * 3 + 2] - Xj[2];
            sD[buf][e] = sqrtf(fmaf(dx, dx, fmaf(dy, dy, fmaf(dz, dz, F_EPS))));
        } else if (e < 19) {
            int nn = e - 16;
            float dt0 = g_t[jb * 3 + 0] - st[0];
            float dt1 = g_t[jb * 3 + 1] - st[1];
            float dt2 = g_t[jb * 3 + 2] - st[2];
            // t_ji[n] = sum_m R[m][n] * dt[m]
            sT[buf][nn] = sR[0 + nn] * dt0 + sR[3 + nn] * dt1 + sR[6 + nn] * dt2;
        }
        __syncthreads();

        float yd = gA + hBj;
#pragma unroll
        for (int c = 0; c < 16; c++) yd = fmaf(sD[buf][c], Wc[c], yd);

        float yv = sT[buf][0] * Wv[0];
        yv = fmaf(sT[buf][1], Wv[1], yv);
        yv = fmaf(sT[buf][2], Wv[2], yv);

        float sv, cv, sd2, cd;
        sincos2pi(yv, sv, cv);
        sincos2pi(yd, sd2, cd);

        size_t ob = ((size_t)(bl * KK + k)) * 256;
        out[ob + e]       = cv + cd;
        out[ob + 128 + e] = sv + sd2;
    }
}

extern "C" void kernel_launch(void* const* d_in, const int* in_sizes, int n_in,
                              void* d_out, int out_size)
{
    const float* X    = (const float*)d_in[0];   // (B,L,4,3) f32
    const int*   eix  = (const int*)  d_in[1];   // (B,L,K) i32
    const int*   Cm   = (const int*)  d_in[2];   // (B,L) i32
    const float* Wvec = (const float*)d_in[3];   // (3,128) f32
    const float* Wd   = (const float*)d_in[4];   // (64,128) f32
    float* out = (float*)d_out;

    k_prep_w<<<1, 128>>>(Wd);
    k_residue<<<BLN, 128>>>(X, Cm);
    k_edges<<<BLN, 128>>>(X, eix, Wvec, out);
}

// round 4
// speedup vs baseline: 1.6714x; 1.6714x over previous
#include <cuda_runtime.h>
#include <cstdint>

#define BB   2
#define LLEN 4096
#define KK   32
#define BLN  (BB * LLEN)   // 8192 residues
#define HALF 128
#define F_EPS 1e-6f

typedef unsigned long long ull;

// -------- scratch (device globals; no allocations allowed) --------
__device__ float g_R  [BLN * 9];
__device__ float g_t  [BLN * 3];
__device__ float g_gA [BLN * HALF];
__device__ float g_hB [BLN * HALF];
__device__ float g_Wc [16 * HALF];
__device__ float g_WiA[ 6 * HALF];
__device__ float g_WiB[ 6 * HALF];
__device__ float g_cw [HALF];

// ---- packed f32x2 helpers ----
__device__ __forceinline__ ull pack2(float lo, float hi) {
    ull r; asm("mov.b64 %0, {%1,%2};" : "=l"(r) : "f"(lo), "f"(hi)); return r;
}
__device__ __forceinline__ void unpack2(ull v, float& lo, float& hi) {
    asm("mov.b64 {%0,%1}, %2;" : "=f"(lo), "=f"(hi) : "l"(v));
}
__device__ __forceinline__ ull fma2(ull a, ull b, ull c) {
    ull d; asm("fma.rn.f32x2 %0, %1, %2, %3;" : "=l"(d) : "l"(a), "l"(b), "l"(c)); return d;
}
__device__ __forceinline__ ull mul2(ull a, ull b) {
    ull d; asm("mul.rn.f32x2 %0, %1, %2;" : "=l"(d) : "l"(a), "l"(b)); return d;
}
__device__ __forceinline__ float xsign(float v, unsigned m) {
    return __uint_as_float(__float_as_uint(v) ^ m);
}

// -------- phase 0: combine W_dist rows (symmetric pairs) --------
__global__ void k_prep_w(const float* __restrict__ Wd) {
    int e = threadIdx.x;
    float cw = 0.f;
#pragma unroll
    for (int a = 0; a < 8; a++) cw += Wd[(a * 8 + a) * HALF + e];
    g_cw[e] = cw * sqrtf(F_EPS);

    const int pa[6] = {0, 0, 0, 1, 1, 2};
    const int pb[6] = {1, 2, 3, 2, 3, 3};
#pragma unroll
    for (int u = 0; u < 6; u++) {
        int a = pa[u], b = pb[u];
        g_WiA[u * HALF + e] = Wd[(a * 8 + b) * HALF + e] + Wd[(b * 8 + a) * HALF + e];
        g_WiB[u * HALF + e] = Wd[((a + 4) * 8 + (b + 4)) * HALF + e]
                            + Wd[((b + 4) * 8 + (a + 4)) * HALF + e];
    }
#pragma unroll
    for (int p = 0; p < 4; p++)
#pragma unroll
        for (int q = 0; q < 4; q++)
            g_Wc[(p * 4 + q) * HALF + e] =
                Wd[(p * 8 + (q + 4)) * HALF + e] + Wd[((q + 4) * 8 + p) * HALF + e];
}

// -------- phase 1: per-residue frames + intra partial sums --------
__global__ void k_residue(const float* __restrict__ X, const int* __restrict__ Cm) {
    int bl = blockIdx.x;
    int e  = threadIdx.x;
    __shared__ float sXi[12];
    if (e < 12) sXi[e] = X[bl * 12 + e];
    __syncthreads();

    float N0 = sXi[0], N1 = sXi[1],  N2 = sXi[2];
    float A0 = sXi[3], A1 = sXi[4],  A2 = sXi[5];
    float C0 = sXi[6], C1 = sXi[7],  C2 = sXi[8];

    float v0 = N0 - A0, v1 = N1 - A1, v2 = N2 - A2;
    float inv = 1.0f / (sqrtf(v0 * v0 + v1 * v1 + v2 * v2) + F_EPS);
    float e10 = v0 * inv, e11 = v1 * inv, e12 = v2 * inv;
    float u0 = C0 - A0, u1 = C1 - A1, u2 = C2 - A2;
    inv = 1.0f / (sqrtf(u0 * u0 + u1 * u1 + u2 * u2) + F_EPS);
    u0 *= inv; u1 *= inv; u2 *= inv;
    float d  = u0 * e10 + u1 * e11 + u2 * e12;
    float w0 = u0 - d * e10, w1 = u1 - d * e11, w2 = u2 - d * e12;
    inv = 1.0f / (sqrtf(w0 * w0 + w1 * w1 + w2 * w2) + F_EPS);
    float e20 = w0 * inv, e21 = w1 * inv, e22 = w2 * inv;
    float e30 = e11 * e22 - e12 * e21;
    float e31 = e12 * e20 - e10 * e22;
    float e32 = e10 * e21 - e11 * e20;

    float mask = (Cm[bl] > 0) ? 1.0f : 0.0f;

    if (e == 0) {
        g_R[bl * 9 + 0] = e10 * mask; g_R[bl * 9 + 1] = e20 * mask; g_R[bl * 9 + 2] = e30 * mask;
        g_R[bl * 9 + 3] = e11 * mask; g_R[bl * 9 + 4] = e21 * mask; g_R[bl * 9 + 5] = e31 * mask;
        g_R[bl * 9 + 6] = e12 * mask; g_R[bl * 9 + 7] = e22 * mask; g_R[bl * 9 + 8] = e32 * mask;
        g_t[bl * 3 + 0] = A0 * mask;  g_t[bl * 3 + 1] = A1 * mask;  g_t[bl * 3 + 2] = A2 * mask;
    }

    const int pa[6] = {0, 0, 0, 1, 1, 2};
    const int pb[6] = {1, 2, 3, 2, 3, 3};
    float d6[6];
#pragma unroll
    for (int u = 0; u < 6; u++) {
        int a = pa[u] * 3, b = pb[u] * 3;
        float dx = sXi[a + 0] - sXi[b + 0];
        float dy = sXi[a + 1] - sXi[b + 1];
        float dz = sXi[a + 2] - sXi[b + 2];
        d6[u] = sqrtf(fmaf(dx, dx, fmaf(dy, dy, fmaf(dz, dz, F_EPS))));
    }
    float gA = g_cw[e];
    float hB = 0.f;
#pragma unroll
    for (int u = 0; u < 6; u++) {
        gA = fmaf(d6[u], g_WiA[u * HALF + e], gA);
        hB = fmaf(d6[u], g_WiB[u * HALF + e], hB);
    }
    g_gA[bl * HALF + e] = gA;
    g_hB[bl * HALF + e] = hB;
}

// -------- phase 2: per-edge fourier features --------
__global__ __launch_bounds__(128) void k_edges(
    const float* __restrict__ X,
    const int*   __restrict__ eidx,
    const float* __restrict__ Wvec,
    float*       __restrict__ out)
{
    int bl = blockIdx.x;
    int e  = threadIdx.x;                      // output channel 0..127
    int b  = bl >> 12;                         // L = 4096

    __shared__ float sXi[12], sR[9], st[3];
    __shared__ int   sjb[KK];
    __shared__ float sXj[KK][12];
    __shared__ float sD[KK][16];               // all cross distances, precomputed
    __shared__ float sT[KK][4];                // all t_ji, precomputed

    if (e < 12) sXi[e] = X[bl * 12 + e];
    if (e < 9)  sR[e]  = g_R[bl * 9 + e];
    if (e < 3)  st[e]  = g_t[bl * 3 + e];
    if (e < KK) sjb[e] = (b << 12) + eidx[bl * KK + e];
    __syncthreads();

    // --- Phase A: cooperative setup, all threads, 2 barriers total ---
    // neighbor coords: 32*12 = 384 floats, 3 per thread
#pragma unroll
    for (int i = 0; i < 3; i++) {
        int idx = e + i * 128;
        int n = idx / 12, c = idx - n * 12;
        sXj[n][c] = X[(size_t)sjb[n] * 12 + c];
    }
    // t_ji per neighbor (threads 0..31, one neighbor each)
    if (e < KK) {
        int jb = sjb[e];
        float dt0 = g_t[jb * 3 + 0] - st[0];
        float dt1 = g_t[jb * 3 + 1] - st[1];
        float dt2 = g_t[jb * 3 + 2] - st[2];
        sT[e][0] = sR[0] * dt0 + sR[3] * dt1 + sR[6] * dt2;
        sT[e][1] = sR[1] * dt0 + sR[4] * dt1 + sR[7] * dt2;
        sT[e][2] = sR[2] * dt0 + sR[5] * dt1 + sR[8] * dt2;
    }
    __syncthreads();

    // all 512 cross distances: 4 per thread
#pragma unroll
    for (int i = 0; i < 4; i++) {
        int idx = e * 4 + i;
        int n = idx >> 4, pq = idx & 15;
        int p = (pq >> 2) * 3, q = (pq & 3) * 3;
        float dx = sXi[p + 0] - sXj[n][q + 0];
        float dy = sXi[p + 1] - sXj[n][q + 1];
        float dz = sXi[p + 2] - sXj[n][q + 2];
        sD[n][pq] = sqrtf(fmaf(dx, dx, fmaf(dy, dy, fmaf(dz, dz, F_EPS))));
    }

    // per-thread invariants
    float Wv0 = Wvec[e], Wv1 = Wvec[HALF + e], Wv2 = Wvec[2 * HALF + e];
    float gA  = g_gA[bl * HALF + e];
    ull Wc2[8];
#pragma unroll
    for (int c = 0; c < 8; c++)
        Wc2[c] = pack2(g_Wc[(2 * c) * HALF + e], g_Wc[(2 * c + 1) * HALF + e]);

    // packed sincos polynomial coefficients (same value in both lanes)
    const ull CC4 = pack2( 60.2446414f,  60.2446414f);
    const ull CC3 = pack2(-85.4568172f, -85.4568172f);
    const ull CC2 = pack2( 64.9393940f,  64.9393940f);
    const ull CC1 = pack2(-19.7392088f, -19.7392088f);
    const ull CC0 = pack2(  1.0f,         1.0f);
    const ull SS4 = pack2( 42.0586939f,  42.0586939f);
    const ull SS3 = pack2(-76.7058598f, -76.7058598f);
    const ull SS2 = pack2( 81.6052493f,  81.6052493f);
    const ull SS1 = pack2(-41.3417022f, -41.3417022f);
    const ull SS0 = pack2(  6.28318531f,  6.28318531f);

    __syncthreads();

    // --- Phase B: pure-compute loop over the K edges ---
    float hbn = g_hB[(size_t)sjb[0] * HALF + e];   // rolling prefetch
#pragma unroll 4
    for (int k = 0; k < KK; k++) {
        float hb = hbn;
        if (k + 1 < KK) hbn = g_hB[(size_t)sjb[k + 1] * HALF + e];

        // yd = gA_i + hB_j + sum_16 cross  (8 packed FMAs)
        ull acc = pack2(gA + hb, 0.0f);
        const float2* dd = (const float2*)sD[k];
#pragma unroll
        for (int c = 0; c < 8; c++) {
            float2 dv = dd[c];                      // LDS.64 broadcast
            acc = fma2(pack2(dv.x, dv.y), Wc2[c], acc);
        }
        float alo, ahi; unpack2(acc, alo, ahi);
        float yd = alo + ahi;

        float yv = fmaf(sT[k][0], Wv0, fmaf(sT[k][1], Wv1, sT[k][2] * Wv2));

        // fused packed sincos(2*pi*{yv, yd})
        int   kv = __float2int_rn(yv + yv);
        int   kd = __float2int_rn(yd + yd);
        float gv = fmaf((float)kv, -0.5f, yv);      // |g| <= 0.25
        float gd = fmaf((float)kd, -0.5f, yd);
        ull g2 = pack2(gv, gd);
        ull t2 = mul2(g2, g2);
        ull cp = fma2(CC4, t2, CC3);
        cp = fma2(cp, t2, CC2);
        cp = fma2(cp, t2, CC1);
        cp = fma2(cp, t2, CC0);
        ull sp = fma2(SS4, t2, SS3);
        sp = fma2(sp, t2, SS2);
        sp = fma2(sp, t2, SS1);
        sp = fma2(sp, t2, SS0);
        sp = mul2(sp, g2);

        float cv, cd, sv, sd;
        unpack2(cp, cv, cd);
        unpack2(sp, sv, sd);
        unsigned mv = ((unsigned)kv) << 31;         // parity of k flips both
        unsigned md = ((unsigned)kd) << 31;

        size_t ob = ((size_t)(bl * KK + k)) * 256;
        out[ob + e]        = xsign(cv, mv) + xsign(cd, md);
        out[ob + HALF + e] = xsign(sv, mv) + xsign(sd, md);
    }
}

extern "C" void kernel_launch(void* const* d_in, const int* in_sizes, int n_in,
                              void* d_out, int out_size)
{
    const float* X    = (const float*)d_in[0];   // (B,L,4,3) f32
    const int*   eix  = (const int*)  d_in[1];   // (B,L,K) i32
    const int*   Cm   = (const int*)  d_in[2];   // (B,L) i32
    const float* Wvec = (const float*)d_in[3];   // (3,128) f32
    const float* Wd   = (const float*)d_in[4];   // (64,128) f32
    float* out = (float*)d_out;

    k_prep_w<<<1, 128>>>(Wd);
    k_residue<<<BLN, 128>>>(X, Cm);
    k_edges<<<BLN, 128>>>(X, eix, Wvec, out);
}